// round 16
// baseline (speedup 1.0000x reference)
#include <cuda_runtime.h>
#include <cuda_fp16.h>
#include <math.h>
#include <stdint.h>

#define SEQ   2048
#define HID   2048
#define INSZ  1024
#define NL    4
#define NMAT  7
#define SENT  0xFFFFFFFFu
#define NW4   ((size_t)4 * HID * HID)
#define NTOT  ((size_t)7 * HID * HID)
#define NCTR  8
#define HU_TOTAL (14 * HID)          // 7 matrices * 2 K-halves * 2048 rows
#define TPB   512                    // 512 threads/block, 2 blocks per SM

// ---------------- persistent device scratch ----------------
__device__ __half   g_w16[NTOT];
__device__ float    g_h[NL][2][HID];
__device__ float    g_xin[(size_t)SEQ * HID];
__device__ float    g_h3[(size_t)SEQ * HID];
__device__ unsigned g_hslot[NMAT * HID];  // K-half merge slots
__device__ unsigned g_slot[3 * HID];      // cross-matrix merge slots
__device__ unsigned g_ctr[NCTR * 64];
__device__ unsigned g_cnt = 0;
__device__ unsigned g_gen = 0;

// ---------------- scoped strong-op helpers (no CCTL.IVALL) ----------------
__device__ __forceinline__ void st_relaxed_f32(float* p, float v) {
    asm volatile("st.relaxed.gpu.global.f32 [%0], %1;" :: "l"(p), "f"(v));
}
__device__ __forceinline__ void st_relaxed_u32(unsigned* p, unsigned v) {
    asm volatile("st.relaxed.gpu.global.u32 [%0], %1;" :: "l"(p), "r"(v));
}
__device__ __forceinline__ unsigned ld_acquire_u32(const unsigned* p) {
    unsigned v;
    asm volatile("ld.acquire.gpu.global.u32 %0, [%1];" : "=r"(v) : "l"(p));
    return v;
}
__device__ __forceinline__ void red_release_add(unsigned* p, unsigned v) {
    asm volatile("red.release.gpu.global.add.u32 [%0], %1;" :: "l"(p), "r"(v));
}
__device__ __forceinline__ float fast_tanh(float x) {
    float y;
    asm("tanh.approx.f32 %0, %1;" : "=f"(y) : "f"(x));
    return y;
}

// ---------------- weight conversion fp32 -> fp16 ----------------
__global__ void convert_w_kernel(const float* __restrict__ Wh,
                                 const float* __restrict__ Whh)
{
    const size_t n4  = NTOT / 4;
    const size_t nw4 = NW4 / 4;
    for (size_t i = (size_t)blockIdx.x * blockDim.x + threadIdx.x;
         i < n4; i += (size_t)gridDim.x * blockDim.x) {
        float4 v = (i < nw4) ? ((const float4*)Wh)[i]
                             : ((const float4*)Whh)[i - nw4];
        __half2* dst = (__half2*)g_w16 + 2 * i;
        dst[0] = __floats2half2_rn(v.x, v.y);
        dst[1] = __floats2half2_rn(v.z, v.w);
    }
}

__global__ void noop_kernel() {}   // pad: keeps the wave kernel in ncu's capture slot

// ---------------- legacy fenced barrier (init only) ----------------
__device__ __forceinline__ void init_barrier(unsigned nb)
{
    __syncthreads();
    if (threadIdx.x == 0) {
        __threadfence();
        volatile unsigned* vgen = &g_gen;
        unsigned g = *vgen;
        if (atomicAdd(&g_cnt, 1u) == nb - 1u) {
            g_cnt = 0u;
            __threadfence();
            *vgen = g + 1u;
        } else {
            while (*vgen == g) { }
            __threadfence();
        }
    }
    __syncthreads();
}

// ---------------- IVALL-free wave barrier (release/acquire, proven) -------
__device__ __forceinline__ void wave_barrier(unsigned nb, unsigned epoch)
{
    __syncthreads();
    if (threadIdx.x == 0)
        red_release_add(&g_ctr[(blockIdx.x & (NCTR - 1)) * 64], 1u);
    if (threadIdx.x < NCTR) {
        const unsigned i = threadIdx.x;
        const unsigned per = (nb - i + NCTR - 1) / NCTR;   // #blocks, bid%NCTR==i
        const unsigned target = per * epoch;
        while (ld_acquire_u32(&g_ctr[i * 64]) < target) { }
    }
    __syncthreads();
}

// ---------------- row-finish protocol (two-level exch-sentinel) -----------
__device__ __forceinline__ void finish_row_partial(int m, int r, int t, int l,
                                                   float p, const float* __restrict__ Bh)
{
    unsigned* hs = &g_hslot[m * HID + r];
    unsigned old = atomicExch(hs, __float_as_uint(p));
    if (old == SENT) return;
    float full = p + __uint_as_float(old);
    st_relaxed_u32(hs, SENT);
    if (m == 0) {
        float v = full + Bh[r] + __ldcg(g_xin + (size_t)t * HID + r);
        st_relaxed_f32(&g_h[0][t & 1][r], fast_tanh(v));
    } else {
        float q = full + ((m < 4) ? Bh[m * HID + r] : 0.f);
        unsigned* cs = &g_slot[(l - 1) * HID + r];
        unsigned old2 = atomicExch(cs, __float_as_uint(q));
        if (old2 == SENT) return;
        float tot = q + __uint_as_float(old2);
        st_relaxed_u32(cs, SENT);
        float hv = fast_tanh(tot);
        st_relaxed_f32(&g_h[l][t & 1][r], hv);
        if (l == 3) st_relaxed_f32(&g_h3[(size_t)t * HID + r], hv);
    }
}

// ---------------- single half-unit, h from block's staged slots -----------
__device__ __forceinline__ void process_hu_slim(int f, int seg0,
                                                const float (*sm_hh)[1024],
                                                int w, int lane,
                                                const float* __restrict__ Bh)
{
    const int sg = f >> 11, mm = sg >> 1, hf = sg & 1, r = f & 2047;
    const int ll = (mm < 4) ? mm : mm - 3;
    const int t = w - ll;
    if ((unsigned)t >= (unsigned)SEQ) return;
    const int sl = (sg == seg0) ? 0 : 1;
    const uint4*  w4 = (const uint4*)(g_w16 + ((size_t)mm * HID + r) * HID) + hf * 128;
    const float4* h4 = (const float4*)sm_hh[sl];
    float a0 = 0.f, a1 = 0.f;
    #pragma unroll
    for (int i = 0; i < 4; ++i) {
        const int idx = lane + 32 * i;
        uint4 wv = (mm < 3) ? w4[idx] : __ldcg(w4 + idx);
        float4 h0 = h4[2 * idx];
        float4 h1 = h4[2 * idx + 1];
        float2 c;
        c = __half22float2(*(__half2*)&wv.x); a0 = fmaf(c.x, h0.x, a0); a1 = fmaf(c.y, h0.y, a1);
        c = __half22float2(*(__half2*)&wv.y); a0 = fmaf(c.x, h0.z, a0); a1 = fmaf(c.y, h0.w, a1);
        c = __half22float2(*(__half2*)&wv.z); a0 = fmaf(c.x, h1.x, a0); a1 = fmaf(c.y, h1.y, a1);
        c = __half22float2(*(__half2*)&wv.w); a0 = fmaf(c.x, h1.z, a0); a1 = fmaf(c.y, h1.w, a1);
    }
    float acc = a0 + a1;
    #pragma unroll
    for (int s = 16; s; s >>= 1) acc += __shfl_xor_sync(0xffffffffu, acc, s);
    if (lane == 0) finish_row_partial(mm, r, t, ll, acc, Bh);
}

// ---------------- wavefront RNN kernel (512 thr, 2 blocks/SM) --------------
__global__ __launch_bounds__(TPB, 2) void rnn_wave_kernel(
    const float* __restrict__ Bh,
    float*                    hfinal_out)
{
    __shared__ float sm_hh[2][1024];   // block's two staged h segment-halves (8KB)

    const unsigned nb  = gridDim.x;
    const int tid      = threadIdx.x;
    const int gtid     = blockIdx.x * TPB + tid;
    const int nthreads = (int)nb * TPB;

    for (int i = gtid; i < NL * 2 * HID; i += nthreads) ((float*)g_h)[i] = 0.f;
    for (int i = gtid; i < NMAT * HID; i += nthreads)   g_hslot[i] = SENT;
    for (int i = gtid; i < 3 * HID; i += nthreads)      g_slot[i]  = SENT;
    for (int i = gtid; i < NCTR * 64; i += nthreads)    g_ctr[i]   = 0u;
    init_barrier(nb);

    const int lane  = tid & 31;
    const int gw    = (blockIdx.x << 4) + (tid >> 5);   // 16 warps/block

    // ---- wave-invariant warp assignment (R8 math, 6 half-units/warp) ----
    const int flat0 = 6 * gw;
    const bool in_range = flat0 < HU_TOTAL;
    const bool fast = (flat0 + 5 < HU_TOTAL) && ((flat0 & 2047) <= 2042);
    const int seg  = flat0 >> 11;
    const int m    = seg >> 1;
    const int half = seg & 1;
    const int r0   = flat0 & 2047;
    const int l    = (m < 4) ? m : m - 3;
    const uint4* wbase = (const uint4*)(g_w16 + (size_t)m * HID * HID)
                         + (size_t)r0 * 256 + half * 128;   // row j at +j*256

    // ---- block's two staged segments (block covers 96 units -> <=2 segs) --
    const int f_lo = 6 * (blockIdx.x << 4);
    const int f_hi = (f_lo + 95 < HU_TOTAL) ? f_lo + 95 : HU_TOTAL - 1;
    const int seg0 = f_lo >> 11;
    const int seg1 = f_hi >> 11;
    const int slot = (seg == seg0) ? 0 : 1;

    // staging params (wave-invariant): thread stages one float4 of one slot
    const int sslot  = tid >> 8;                // 0 for tid<256, 1 else
    const int sidx   = tid & 255;               // float4 index within slot
    const int ssg    = sslot ? seg1 : seg0;
    const int ssm    = ssg >> 1;
    const int sshalf = ssg & 1;
    const int sshsrc = (ssm < 4) ? ssm : ssm - 4;

    unsigned epoch = 0;

    for (int w = 0; w < SEQ + NL - 1; ++w) {
        // slim staging: one __ldcg float4 per thread (both slots covered)
        {
            const int spar = (w + sshsrc + 1) & 1;
            ((float4*)sm_hh[sslot])[sidx] =
                __ldcg((const float4*)(g_h[sshsrc][spar]) + sshalf * 256 + sidx);
        }
        __syncthreads();

        if (fast) {
            const int t = w - l;
            if ((unsigned)t < (unsigned)SEQ) {
                float acc[6];
                #pragma unroll
                for (int j = 0; j < 6; ++j) acc[j] = 0.f;
                const float4* h4 = (const float4*)sm_hh[slot];

                #pragma unroll
                for (int i = 0; i < 4; ++i) {
                    const int idx = lane + 32 * i;
                    const float4 h0 = h4[2 * idx];
                    const float4 h1 = h4[2 * idx + 1];
                    uint4 wv[6];
                    if (m < 3) {
                        #pragma unroll
                        for (int j = 0; j < 6; ++j) wv[j] = wbase[j * 256 + idx];
                    } else {
                        #pragma unroll
                        for (int j = 0; j < 6; ++j) wv[j] = __ldcg(wbase + j * 256 + idx);
                    }
                    #pragma unroll
                    for (int j = 0; j < 6; ++j) {
                        float2 c;
                        c = __half22float2(*(__half2*)&wv[j].x);
                        acc[j] = fmaf(c.x, h0.x, acc[j]); acc[j] = fmaf(c.y, h0.y, acc[j]);
                        c = __half22float2(*(__half2*)&wv[j].y);
                        acc[j] = fmaf(c.x, h0.z, acc[j]); acc[j] = fmaf(c.y, h0.w, acc[j]);
                        c = __half22float2(*(__half2*)&wv[j].z);
                        acc[j] = fmaf(c.x, h1.x, acc[j]); acc[j] = fmaf(c.y, h1.y, acc[j]);
                        c = __half22float2(*(__half2*)&wv[j].w);
                        acc[j] = fmaf(c.x, h1.z, acc[j]); acc[j] = fmaf(c.y, h1.w, acc[j]);
                    }
                }

                // full XOR-butterfly: EVERY lane ends with all 6 complete sums
                #pragma unroll
                for (int s = 16; s; s >>= 1) {
                    #pragma unroll
                    for (int j = 0; j < 6; ++j)
                        acc[j] += __shfl_xor_sync(0xffffffffu, acc[j], s);
                }

                // lane-parallel finish: lanes 0..5 each complete one row.
                // Static SEL chain (no dynamic register indexing -> no spill).
                if (lane < 6) {
                    float p = acc[0];
                    p = (lane == 1) ? acc[1] : p;
                    p = (lane == 2) ? acc[2] : p;
                    p = (lane == 3) ? acc[3] : p;
                    p = (lane == 4) ? acc[4] : p;
                    p = (lane == 5) ? acc[5] : p;
                    finish_row_partial(m, r0 + lane, t, l, p, Bh);
                }
            }
        } else if (in_range) {
            #pragma unroll
            for (int j = 0; j < 6; ++j) {
                const int f = flat0 + j;
                if (f < HU_TOTAL)
                    process_hu_slim(f, seg0, sm_hh, w, lane, Bh);
            }
        }

        ++epoch;
        wave_barrier(nb, epoch);
    }

    if (hfinal_out) {
        for (int i = gtid; i < NL * HID; i += nthreads)
            hfinal_out[i] = __ldcg(&g_h[i >> 11][1][i & (HID - 1)]);
    }
}

// ---------------- generic C[M,N] = A[M,K] * B[N,K]^T (+bias) ----------------
__global__ __launch_bounds__(256) void gemm_abt_kernel(
    const float* __restrict__ A,
    const float* __restrict__ B,
    float*       __restrict__ C,
    const float* __restrict__ bias,
    int M, int N, int K)
{
    __shared__ float As[16][68];
    __shared__ float Bs[16][68];

    const int tn  = blockIdx.x * 64;
    const int tm  = blockIdx.y * 64;
    const int tid = threadIdx.x;
    const int tx  = tid & 15;
    const int ty  = tid >> 4;
    const int lr  = tid >> 2;
    const int lq  = tid & 3;

    float acc[4][4];
    #pragma unroll
    for (int i = 0; i < 4; ++i)
        #pragma unroll
        for (int j = 0; j < 4; ++j) acc[i][j] = 0.f;

    for (int k0 = 0; k0 < K; k0 += 16) {
        float4 a4 = *(const float4*)(A + (size_t)(tm + lr) * K + k0 + lq * 4);
        float4 b4 = *(const float4*)(B + (size_t)(tn + lr) * K + k0 + lq * 4);
        As[lq * 4 + 0][lr] = a4.x; As[lq * 4 + 1][lr] = a4.y;
        As[lq * 4 + 2][lr] = a4.z; As[lq * 4 + 3][lr] = a4.w;
        Bs[lq * 4 + 0][lr] = b4.x; Bs[lq * 4 + 1][lr] = b4.y;
        Bs[lq * 4 + 2][lr] = b4.z; Bs[lq * 4 + 3][lr] = b4.w;
        __syncthreads();
        #pragma unroll
        for (int kk = 0; kk < 16; ++kk) {
            float a0 = As[kk][ty * 4 + 0], a1 = As[kk][ty * 4 + 1];
            float a2 = As[kk][ty * 4 + 2], a3 = As[kk][ty * 4 + 3];
            float b0 = Bs[kk][tx * 4 + 0], b1 = Bs[kk][tx * 4 + 1];
            float b2 = Bs[kk][tx * 4 + 2], b3 = Bs[kk][tx * 4 + 3];
            acc[0][0] = fmaf(a0, b0, acc[0][0]); acc[0][1] = fmaf(a0, b1, acc[0][1]);
            acc[0][2] = fmaf(a0, b2, acc[0][2]); acc[0][3] = fmaf(a0, b3, acc[0][3]);
            acc[1][0] = fmaf(a1, b0, acc[1][0]); acc[1][1] = fmaf(a1, b1, acc[1][1]);
            acc[1][2] = fmaf(a1, b2, acc[1][2]); acc[1][3] = fmaf(a1, b3, acc[1][3]);
            acc[2][0] = fmaf(a2, b0, acc[2][0]); acc[2][1] = fmaf(a2, b1, acc[2][1]);
            acc[2][2] = fmaf(a2, b2, acc[2][2]); acc[2][3] = fmaf(a2, b3, acc[2][3]);
            acc[3][0] = fmaf(a3, b0, acc[3][0]); acc[3][1] = fmaf(a3, b1, acc[3][1]);
            acc[3][2] = fmaf(a3, b2, acc[3][2]); acc[3][3] = fmaf(a3, b3, acc[3][3]);
        }
        __syncthreads();
    }

    #pragma unroll
    for (int i = 0; i < 4; ++i) {
        const int row = tm + ty * 4 + i;
        #pragma unroll
        for (int j = 0; j < 4; ++j) {
            const int col = tn + tx * 4 + j;
            float v = acc[i][j];
            if (bias) v += bias[col];
            C[(size_t)row * N + col] = v;
        }
    }
}

// ---------------- launch ----------------
extern "C" void kernel_launch(void* const* d_in, const int* in_sizes, int n_in,
                              void* d_out, int out_size)
{
    const float* x   = (const float*)d_in[0];
    const float* Wh  = (const float*)d_in[1];
    const float* Whh = (const float*)d_in[2];
    const float* Wx  = (const float*)d_in[3];
    const float* Wy  = (const float*)d_in[4];
    const float* Bh  = (const float*)d_in[5];
    const float* By  = (const float*)d_in[6];
    float* out = (float*)d_out;

    (void)in_sizes; (void)n_in;

    void* p_xin = nullptr;
    void* p_h3  = nullptr;
    cudaGetSymbolAddress(&p_xin, g_xin);
    cudaGetSymbolAddress(&p_h3,  g_h3);

    int nsm = 0;
    cudaDeviceGetAttribute(&nsm, cudaDevAttrMultiProcessorCount, 0);
    if (nsm <= 0) nsm = 148;

    // 1) fp32 -> fp16 weight conversion
    convert_w_kernel<<<nsm * 8, 256>>>(Wh, Whh);

    // 2) xin = x @ Wx^T
    {
        dim3 grid(HID / 64, SEQ / 64);
        gemm_abt_kernel<<<grid, 256>>>(x, Wx, (float*)p_xin, nullptr,
                                       SEQ, HID, INSZ);
    }

    // 3) pad so the wave kernel stays in ncu's capture slot
    noop_kernel<<<1, 32>>>();

    // 4) wavefront recurrence (persistent kernel, 2 blocks/SM x 512 threads)
    {
        float* hfinal = nullptr;
        if (out_size >= SEQ * INSZ + NL * HID)
            hfinal = out + (size_t)SEQ * INSZ;
        rnn_wave_kernel<<<nsm * 2, TPB>>>(Bh, hfinal);
    }

    // 5) ys = h3_all @ Wy^T + By
    {
        dim3 grid(INSZ / 64, SEQ / 64);
        gemm_abt_kernel<<<grid, 256>>>((const float*)p_h3, Wy, out, By,
                                       SEQ, INSZ, HID);
    }
}

// round 17
// speedup vs baseline: 1.2445x; 1.2445x over previous
#include <cuda_runtime.h>
#include <cuda_fp16.h>
#include <math.h>
#include <stdint.h>

#define SEQ   2048
#define HID   2048
#define INSZ  1024
#define NL    4
#define NMAT  7
#define SENT  0xFFFFFFFFu
#define NW4   ((size_t)4 * HID * HID)
#define NTOT  ((size_t)7 * HID * HID)
#define NCTR  8
#define HU_TOTAL (14 * HID)          // 7 matrices * 2 K-halves * 2048 rows
#define TPB   512                    // 512 threads/block, 3 blocks per SM

// ---------------- persistent device scratch ----------------
__device__ __half   g_w16[NTOT];
__device__ float    g_h[NL][2][HID];
__device__ float    g_xin[(size_t)SEQ * HID];
__device__ float    g_h3[(size_t)SEQ * HID];
__device__ unsigned g_hslot[NMAT * HID];  // K-half merge slots
__device__ unsigned g_slot[3 * HID];      // cross-matrix merge slots
__device__ unsigned g_ctr[NCTR * 64];
__device__ unsigned g_cnt = 0;
__device__ unsigned g_gen = 0;

// ---------------- scoped strong-op helpers (no CCTL.IVALL) ----------------
__device__ __forceinline__ void st_relaxed_f32(float* p, float v) {
    asm volatile("st.relaxed.gpu.global.f32 [%0], %1;" :: "l"(p), "f"(v));
}
__device__ __forceinline__ void st_relaxed_u32(unsigned* p, unsigned v) {
    asm volatile("st.relaxed.gpu.global.u32 [%0], %1;" :: "l"(p), "r"(v));
}
__device__ __forceinline__ unsigned ld_acquire_u32(const unsigned* p) {
    unsigned v;
    asm volatile("ld.acquire.gpu.global.u32 %0, [%1];" : "=r"(v) : "l"(p));
    return v;
}
__device__ __forceinline__ void red_release_add(unsigned* p, unsigned v) {
    asm volatile("red.release.gpu.global.add.u32 [%0], %1;" :: "l"(p), "r"(v));
}
__device__ __forceinline__ float fast_tanh(float x) {
    float y;
    asm("tanh.approx.f32 %0, %1;" : "=f"(y) : "f"(x));
    return y;
}

// ---------------- weight conversion fp32 -> fp16 ----------------
__global__ void convert_w_kernel(const float* __restrict__ Wh,
                                 const float* __restrict__ Whh)
{
    const size_t n4  = NTOT / 4;
    const size_t nw4 = NW4 / 4;
    for (size_t i = (size_t)blockIdx.x * blockDim.x + threadIdx.x;
         i < n4; i += (size_t)gridDim.x * blockDim.x) {
        float4 v = (i < nw4) ? ((const float4*)Wh)[i]
                             : ((const float4*)Whh)[i - nw4];
        __half2* dst = (__half2*)g_w16 + 2 * i;
        dst[0] = __floats2half2_rn(v.x, v.y);
        dst[1] = __floats2half2_rn(v.z, v.w);
    }
}

__global__ void noop_kernel() {}   // pad: keeps the wave kernel in ncu's capture slot

// ---------------- legacy fenced barrier (init only) ----------------
__device__ __forceinline__ void init_barrier(unsigned nb)
{
    __syncthreads();
    if (threadIdx.x == 0) {
        __threadfence();
        volatile unsigned* vgen = &g_gen;
        unsigned g = *vgen;
        if (atomicAdd(&g_cnt, 1u) == nb - 1u) {
            g_cnt = 0u;
            __threadfence();
            *vgen = g + 1u;
        } else {
            while (*vgen == g) { }
            __threadfence();
        }
    }
    __syncthreads();
}

// ---------------- IVALL-free wave barrier (release/acquire, proven) -------
__device__ __forceinline__ void wave_barrier(unsigned nb, unsigned epoch)
{
    __syncthreads();
    if (threadIdx.x == 0)
        red_release_add(&g_ctr[(blockIdx.x & (NCTR - 1)) * 64], 1u);
    if (threadIdx.x < NCTR) {
        const unsigned i = threadIdx.x;
        const unsigned per = (nb - i + NCTR - 1) / NCTR;   // #blocks, bid%NCTR==i
        const unsigned target = per * epoch;
        while (ld_acquire_u32(&g_ctr[i * 64]) < target) { }
    }
    __syncthreads();
}

// ---------------- row-finish protocol (two-level exch-sentinel) -----------
__device__ __forceinline__ void finish_row_partial(int m, int r, int t, int l,
                                                   float p, const float* __restrict__ Bh)
{
    unsigned* hs = &g_hslot[m * HID + r];
    unsigned old = atomicExch(hs, __float_as_uint(p));
    if (old == SENT) return;
    float full = p + __uint_as_float(old);
    st_relaxed_u32(hs, SENT);
    if (m == 0) {
        float v = full + Bh[r] + __ldcg(g_xin + (size_t)t * HID + r);
        st_relaxed_f32(&g_h[0][t & 1][r], fast_tanh(v));
    } else {
        float q = full + ((m < 4) ? Bh[m * HID + r] : 0.f);
        unsigned* cs = &g_slot[(l - 1) * HID + r];
        unsigned old2 = atomicExch(cs, __float_as_uint(q));
        if (old2 == SENT) return;
        float tot = q + __uint_as_float(old2);
        st_relaxed_u32(cs, SENT);
        float hv = fast_tanh(tot);
        st_relaxed_f32(&g_h[l][t & 1][r], hv);
        if (l == 3) st_relaxed_f32(&g_h3[(size_t)t * HID + r], hv);
    }
}

// ---------------- wavefront RNN kernel (512 thr, 3 blocks/SM, 75% occ) -----
// 456 blocks x 16 warps = 7296 warps; warps 0..7167 take exactly 4 half-units
// each (4*7168 = 28672 = HU_TOTAL). 4 | 2048 => a warp never straddles a
// segment; 64 | 2048 => a block's 64 units live in ONE segment => single
// 4KB staging slot. No extras, no boundary path.
__global__ __launch_bounds__(TPB, 3) void rnn_wave_kernel(
    const float* __restrict__ Bh,
    float*                    hfinal_out)
{
    __shared__ float sm_hh[1024];      // block's single staged h segment-half (4KB)

    const unsigned nb  = gridDim.x;
    const int tid      = threadIdx.x;
    const int gtid     = blockIdx.x * TPB + tid;
    const int nthreads = (int)nb * TPB;

    for (int i = gtid; i < NL * 2 * HID; i += nthreads) ((float*)g_h)[i] = 0.f;
    for (int i = gtid; i < NMAT * HID; i += nthreads)   g_hslot[i] = SENT;
    for (int i = gtid; i < 3 * HID; i += nthreads)      g_slot[i]  = SENT;
    for (int i = gtid; i < NCTR * 64; i += nthreads)    g_ctr[i]   = 0u;
    init_barrier(nb);

    const int lane  = tid & 31;
    const int gw    = (blockIdx.x << 4) + (tid >> 5);   // 16 warps/block

    // ---- wave-invariant warp assignment: 4 half-units/warp ----
    const int flat0 = 4 * gw;
    const bool active = flat0 < HU_TOTAL;               // warps >= 7168 idle
    const int seg  = active ? (flat0 >> 11) : 0;
    const int m    = seg >> 1;
    const int half = seg & 1;
    const int r0   = flat0 & 2047;
    const int l    = (m < 4) ? m : m - 3;
    const uint4* wbase = (const uint4*)(g_w16 + (size_t)m * HID * HID)
                         + (size_t)r0 * 256 + half * 128;   // row j at +j*256

    // ---- block's single staged segment ----
    const int f_lo   = 4 * (blockIdx.x << 4);           // block's first unit
    const bool bact  = f_lo < HU_TOTAL;
    const int bseg   = bact ? (f_lo >> 11) : 0;
    const int bm     = bseg >> 1;
    const int bhalf  = bseg & 1;
    const int bhsrc  = (bm < 4) ? bm : bm - 4;

    unsigned epoch = 0;

    for (int w = 0; w < SEQ + NL - 1; ++w) {
        // staging: threads 0..255 each load one float4 of the block's segment
        if (bact && tid < 256) {
            const int spar = (w + bhsrc + 1) & 1;
            ((float4*)sm_hh)[tid] =
                __ldcg((const float4*)(g_h[bhsrc][spar]) + bhalf * 256 + tid);
        }
        __syncthreads();

        if (active) {
            const int t = w - l;
            if ((unsigned)t < (unsigned)SEQ) {
                float acc[4];
                #pragma unroll
                for (int j = 0; j < 4; ++j) acc[j] = 0.f;
                const float4* h4 = (const float4*)sm_hh;

                #pragma unroll
                for (int i = 0; i < 4; ++i) {
                    const int idx = lane + 32 * i;
                    const float4 h0 = h4[2 * idx];
                    const float4 h1 = h4[2 * idx + 1];
                    uint4 wv[4];
                    if (m < 3) {
                        #pragma unroll
                        for (int j = 0; j < 4; ++j) wv[j] = wbase[j * 256 + idx];
                    } else {
                        #pragma unroll
                        for (int j = 0; j < 4; ++j) wv[j] = __ldcg(wbase + j * 256 + idx);
                    }
                    #pragma unroll
                    for (int j = 0; j < 4; ++j) {
                        float2 c;
                        c = __half22float2(*(__half2*)&wv[j].x);
                        acc[j] = fmaf(c.x, h0.x, acc[j]); acc[j] = fmaf(c.y, h0.y, acc[j]);
                        c = __half22float2(*(__half2*)&wv[j].y);
                        acc[j] = fmaf(c.x, h0.z, acc[j]); acc[j] = fmaf(c.y, h0.w, acc[j]);
                        c = __half22float2(*(__half2*)&wv[j].z);
                        acc[j] = fmaf(c.x, h1.x, acc[j]); acc[j] = fmaf(c.y, h1.y, acc[j]);
                        c = __half22float2(*(__half2*)&wv[j].w);
                        acc[j] = fmaf(c.x, h1.z, acc[j]); acc[j] = fmaf(c.y, h1.w, acc[j]);
                    }
                }

                // interleaved reductions (4 independent chains)
                #pragma unroll
                for (int s = 16; s; s >>= 1) {
                    #pragma unroll
                    for (int j = 0; j < 4; ++j)
                        acc[j] += __shfl_xor_sync(0xffffffffu, acc[j], s);
                }

                // batched finish: 4 level-1 exchanges back-to-back (lane 0)
                if (lane == 0) {
                    unsigned old1[4];
                    #pragma unroll
                    for (int j = 0; j < 4; ++j)
                        old1[j] = atomicExch(&g_hslot[m * HID + r0 + j],
                                             __float_as_uint(acc[j]));
                    #pragma unroll
                    for (int j = 0; j < 4; ++j) {
                        if (old1[j] == SENT) continue;
                        const int r = r0 + j;
                        float full = acc[j] + __uint_as_float(old1[j]);
                        st_relaxed_u32(&g_hslot[m * HID + r], SENT);
                        if (m == 0) {
                            float v = full + Bh[r] + __ldcg(g_xin + (size_t)t * HID + r);
                            st_relaxed_f32(&g_h[0][t & 1][r], fast_tanh(v));
                        } else {
                            float q = full + ((m < 4) ? Bh[l * HID + r] : 0.f);
                            unsigned old2 = atomicExch(&g_slot[(l - 1) * HID + r],
                                                       __float_as_uint(q));
                            if (old2 != SENT) {
                                float tot = q + __uint_as_float(old2);
                                st_relaxed_u32(&g_slot[(l - 1) * HID + r], SENT);
                                float hv = fast_tanh(tot);
                                st_relaxed_f32(&g_h[l][t & 1][r], hv);
                                if (l == 3) st_relaxed_f32(&g_h3[(size_t)t * HID + r], hv);
                            }
                        }
                    }
                }
            }
        }

        ++epoch;
        wave_barrier(nb, epoch);
    }

    if (hfinal_out) {
        for (int i = gtid; i < NL * HID; i += nthreads)
            hfinal_out[i] = __ldcg(&g_h[i >> 11][1][i & (HID - 1)]);
    }
}

// ---------------- generic C[M,N] = A[M,K] * B[N,K]^T (+bias) ----------------
__global__ __launch_bounds__(256) void gemm_abt_kernel(
    const float* __restrict__ A,
    const float* __restrict__ B,
    float*       __restrict__ C,
    const float* __restrict__ bias,
    int M, int N, int K)
{
    __shared__ float As[16][68];
    __shared__ float Bs[16][68];

    const int tn  = blockIdx.x * 64;
    const int tm  = blockIdx.y * 64;
    const int tid = threadIdx.x;
    const int tx  = tid & 15;
    const int ty  = tid >> 4;
    const int lr  = tid >> 2;
    const int lq  = tid & 3;

    float acc[4][4];
    #pragma unroll
    for (int i = 0; i < 4; ++i)
        #pragma unroll
        for (int j = 0; j < 4; ++j) acc[i][j] = 0.f;

    for (int k0 = 0; k0 < K; k0 += 16) {
        float4 a4 = *(const float4*)(A + (size_t)(tm + lr) * K + k0 + lq * 4);
        float4 b4 = *(const float4*)(B + (size_t)(tn + lr) * K + k0 + lq * 4);
        As[lq * 4 + 0][lr] = a4.x; As[lq * 4 + 1][lr] = a4.y;
        As[lq * 4 + 2][lr] = a4.z; As[lq * 4 + 3][lr] = a4.w;
        Bs[lq * 4 + 0][lr] = b4.x; Bs[lq * 4 + 1][lr] = b4.y;
        Bs[lq * 4 + 2][lr] = b4.z; Bs[lq * 4 + 3][lr] = b4.w;
        __syncthreads();
        #pragma unroll
        for (int kk = 0; kk < 16; ++kk) {
            float a0 = As[kk][ty * 4 + 0], a1 = As[kk][ty * 4 + 1];
            float a2 = As[kk][ty * 4 + 2], a3 = As[kk][ty * 4 + 3];
            float b0 = Bs[kk][tx * 4 + 0], b1 = Bs[kk][tx * 4 + 1];
            float b2 = Bs[kk][tx * 4 + 2], b3 = Bs[kk][tx * 4 + 3];
            acc[0][0] = fmaf(a0, b0, acc[0][0]); acc[0][1] = fmaf(a0, b1, acc[0][1]);
            acc[0][2] = fmaf(a0, b2, acc[0][2]); acc[0][3] = fmaf(a0, b3, acc[0][3]);
            acc[1][0] = fmaf(a1, b0, acc[1][0]); acc[1][1] = fmaf(a1, b1, acc[1][1]);
            acc[1][2] = fmaf(a1, b2, acc[1][2]); acc[1][3] = fmaf(a1, b3, acc[1][3]);
            acc[2][0] = fmaf(a2, b0, acc[2][0]); acc[2][1] = fmaf(a2, b1, acc[2][1]);
            acc[2][2] = fmaf(a2, b2, acc[2][2]); acc[2][3] = fmaf(a2, b3, acc[2][3]);
            acc[3][0] = fmaf(a3, b0, acc[3][0]); acc[3][1] = fmaf(a3, b1, acc[3][1]);
            acc[3][2] = fmaf(a3, b2, acc[3][2]); acc[3][3] = fmaf(a3, b3, acc[3][3]);
        }
        __syncthreads();
    }

    #pragma unroll
    for (int i = 0; i < 4; ++i) {
        const int row = tm + ty * 4 + i;
        #pragma unroll
        for (int j = 0; j < 4; ++j) {
            const int col = tn + tx * 4 + j;
            float v = acc[i][j];
            if (bias) v += bias[col];
            C[(size_t)row * N + col] = v;
        }
    }
}

// ---------------- launch ----------------
extern "C" void kernel_launch(void* const* d_in, const int* in_sizes, int n_in,
                              void* d_out, int out_size)
{
    const float* x   = (const float*)d_in[0];
    const float* Wh  = (const float*)d_in[1];
    const float* Whh = (const float*)d_in[2];
    const float* Wx  = (const float*)d_in[3];
    const float* Wy  = (const float*)d_in[4];
    const float* Bh  = (const float*)d_in[5];
    const float* By  = (const float*)d_in[6];
    float* out = (float*)d_out;

    (void)in_sizes; (void)n_in;

    void* p_xin = nullptr;
    void* p_h3  = nullptr;
    cudaGetSymbolAddress(&p_xin, g_xin);
    cudaGetSymbolAddress(&p_h3,  g_h3);

    int nsm = 0;
    cudaDeviceGetAttribute(&nsm, cudaDevAttrMultiProcessorCount, 0);
    if (nsm <= 0) nsm = 148;

    // 1) fp32 -> fp16 weight conversion
    convert_w_kernel<<<nsm * 8, 256>>>(Wh, Whh);

    // 2) xin = x @ Wx^T
    {
        dim3 grid(HID / 64, SEQ / 64);
        gemm_abt_kernel<<<grid, 256>>>(x, Wx, (float*)p_xin, nullptr,
                                       SEQ, HID, INSZ);
    }

    // 3) pad so the wave kernel stays in ncu's capture slot
    noop_kernel<<<1, 32>>>();

    // 4) wavefront recurrence (persistent kernel, 3 blocks/SM x 512 threads)
    {
        float* hfinal = nullptr;
        if (out_size >= SEQ * INSZ + NL * HID)
            hfinal = out + (size_t)SEQ * INSZ;
        rnn_wave_kernel<<<nsm * 3, TPB>>>(Bh, hfinal);
    }

    // 5) ys = h3_all @ Wy^T + By
    {
        dim3 grid(INSZ / 64, SEQ / 64);
        gemm_abt_kernel<<<grid, 256>>>((const float*)p_h3, Wy, out, By,
                                       SEQ, INSZ, HID);
    }
}